// round 9
// baseline (speedup 1.0000x reference)
#include <cuda_runtime.h>
#include <cuda_bf16.h>

// CRF NLL: B=512, S=1024, T=64.
// inputs: 0 emissions (B,S,T) f32, 1 tags (B,S) i32, 2 mask (B,S) i32,
//         3 start (T) f32, 4 end (T) f32, 5 transitions (T,T) f32
// output: scalar f32 = -(sum_b ll_b) / (sum_b L_b)
//
// Forward-backward split (Z = alpha_mid . beta_mid), scaled linear domain.
// The whole per-step update path is bf16: matvec (HFMA2) -> PRMT pair-sum ->
// HMUL2 by Fr2=bf16(exp(em)*2^-k) -> STS.32. Rescale exponent sampled from
// bf16 bits of w[0] (stable frac recurrence). 16 warps/block x 64 blocks
// -> 4 independent chains per SMSP to cover the dependent-chain latency.

#define B_ 512
#define S_ 1024
#define T_ 64
#define FULLMASK 0xffffffffu

__device__ float g_ll[B_];
__device__ float g_len[B_];

typedef __nv_bfloat162 bf2;

__device__ __forceinline__ bf2 bf2pack(float lo, float hi) {
    return __float22bfloat162_rn(make_float2(lo, hi));
}
__device__ __forceinline__ unsigned bf2bits(bf2 v) {
    unsigned u;
    asm("mov.b32 %0, %1;" : "=r"(u) : "r"(*(unsigned*)&v));
    return u;
}
__device__ __forceinline__ bf2 bits2bf2(unsigned u) {
    bf2 v;
    *(unsigned*)&v = u;
    return v;
}

// 16 warps/block = 8 batches/block (fwd+bwd warp per batch). grid = 64.
__global__ void __launch_bounds__(512) crf_main(
    const float* __restrict__ emis,
    const int* __restrict__ tags,
    const int* __restrict__ mask,
    const float* __restrict__ start,
    const float* __restrict__ endt,
    const float* __restrict__ trans)
{
    __shared__ __align__(16) bf2 sh_w[16][2][32];    // per-warp exchange (bf16)
    __shared__ __align__(16) float sh_a[8][T_];      // forward's alpha_mid (f32)
    __shared__ float sh_sc[8][2];                    // [pair][{csF, numF}]

    const int lane = threadIdx.x & 31;
    const int wid  = threadIdx.x >> 5;
    const int pair = wid >> 1;      // 0..7
    const int role = wid & 1;       // 0 = forward, 1 = backward
    const int b    = blockIdx.x * 8 + pair;

    const int j0 = 2 * lane;
    const int j1 = j0 + 1;

    const int base = b * S_;
    const float* em = emis + (size_t)base * T_;
    const float2* ep = (const float2*)em;

    // ---- sequence length L (prefix mask) ----
    int lp = 0;
#pragma unroll 4
    for (int s = lane; s < S_; s += 32) lp += mask[base + s];
#pragma unroll
    for (int o = 16; o > 0; o >>= 1) lp += __shfl_xor_sync(FULLMASK, lp, o);
    const int L = lp;
    const int mid = L >> 1;

    if (role == 0) {
        // ================= FORWARD: alpha over s = 0..mid =================
        bf2 Ej0[T_ / 2];
        bf2 Ej1[T_ / 2];
#pragma unroll
        for (int m = 0; m < T_ / 2; m++) {
            float2 ra = *(const float2*)&trans[(2 * m) * T_ + j0];
            float2 rb = *(const float2*)&trans[(2 * m + 1) * T_ + j0];
            Ej0[m] = bf2pack(__expf(ra.x), __expf(rb.x));
            Ej1[m] = bf2pack(__expf(ra.y), __expf(rb.y));
        }

        // numerator over s in [1, mid]
        float num = 0.0f;
        for (int s = 1 + lane; s <= mid; s += 32) {
            int tp = tags[base + s - 1];
            int tc = tags[base + s];
            num += trans[tp * T_ + tc] + em[s * T_ + tc];
        }
#pragma unroll
        for (int o = 16; o > 0; o >>= 1) num += __shfl_xor_sync(FULLMASK, num, o);
        if (lane == 0) {
            int tg0 = tags[base];
            num += start[tg0] + em[tg0];
        }

        // init: w_0 = exp(start + em_0)
        float2 e0 = ep[lane];
        float w0f = __expf(start[j0] + e0.x);
        float w1f = __expf(start[j1] + e0.y);
        bf2 w2 = bf2pack(w0f, w1f);

        float2 p1 = ep[1 * (T_ / 2) + lane];
        float2 p2 = ep[2 * (T_ / 2) + lane];

        float r;
        int   kpend;
        {
            float w00 = __shfl_sync(FULLMASK, w0f, 0);
            int k = ((__float_as_int(w00) >> 23) & 0xff) - 127;
            k = max(-126, min(126, k));
            r = __int_as_float((127 - k) << 23);
            kpend = k;
        }
        float csum = 0.0f;

        const bf2 z2 = bf2pack(0.0f, 0.0f);

        for (int s = 1; s <= mid; s++) {
            const int pb = s & 1;
            sh_w[wid][pb][lane] = w2;
            __syncwarp();

            // F_s = exp(em[s]) (p1 currently holds em[s]); advance prefetch
            float Fn0 = __expf(p1.x);
            float Fn1 = __expf(p1.y);
            p1 = p2;
            int sp = s + 2; if (sp >= S_) sp = S_ - 1;
            p2 = ep[sp * (T_ / 2) + lane];
            bf2 Fr2 = bf2pack(Fn0 * r, Fn1 * r);  // off-chain vs matvec

            const uint4* q = (const uint4*)sh_w[wid][pb];
            bf2 a00 = z2, a01 = z2, a02 = z2, a03 = z2;    // output j0
            bf2 a10 = z2, a11 = z2, a12 = z2, a13 = z2;    // output j1
#pragma unroll
            for (int g = 0; g < 8; g++) {
                uint4 v = q[g];
                bf2 ws0 = bits2bf2(v.x);
                bf2 ws1 = bits2bf2(v.y);
                bf2 ws2 = bits2bf2(v.z);
                bf2 ws3 = bits2bf2(v.w);
                a00 = __hfma2(ws0, Ej0[4 * g + 0], a00);
                a01 = __hfma2(ws1, Ej0[4 * g + 1], a01);
                a02 = __hfma2(ws2, Ej0[4 * g + 2], a02);
                a03 = __hfma2(ws3, Ej0[4 * g + 3], a03);
                a10 = __hfma2(ws0, Ej1[4 * g + 0], a10);
                a11 = __hfma2(ws1, Ej1[4 * g + 1], a11);
                a12 = __hfma2(ws2, Ej1[4 * g + 2], a12);
                a13 = __hfma2(ws3, Ej1[4 * g + 3], a13);
            }
            bf2 s0 = __hadd2(__hadd2(a00, a01), __hadd2(a02, a03));
            bf2 s1 = __hadd2(__hadd2(a10, a11), __hadd2(a12, a13));
            unsigned u0 = bf2bits(s0), u1 = bf2bits(s1);
            bf2 lo2 = bits2bf2(__byte_perm(u0, u1, 0x5410)); // (s0.lo, s1.lo)
            bf2 hi2 = bits2bf2(__byte_perm(u0, u1, 0x7632)); // (s0.hi, s1.hi)
            w2 = __hmul2(__hadd2(lo2, hi2), Fr2);

            csum += (float)kpend;

            unsigned uw = __shfl_sync(FULLMASK, bf2bits(w2), 0);
            int k = (int)((uw >> 7) & 0xff) - 127;   // bf16 exponent of w[0]
            k = max(-126, min(126, k));
            r = __int_as_float((127 - k) << 23);
            kpend = k;
        }

        // publish alpha_mid (scaled) + scalars
        float2 af = __bfloat1622float2(w2);
        *(float2*)&sh_a[pair][j0] = af;
        if (lane == 0) {
            sh_sc[pair][0] = csum;
            sh_sc[pair][1] = num;
        }
    } else {
        // ================= BACKWARD: beta over s = L-1..mid =================
        bf2 Ri0[T_ / 2];
        bf2 Ri1[T_ / 2];
#pragma unroll
        for (int m = 0; m < T_ / 2; m++) {
            float2 ra = *(const float2*)&trans[j0 * T_ + 2 * m];
            float2 rb = *(const float2*)&trans[j1 * T_ + 2 * m];
            Ri0[m] = bf2pack(__expf(ra.x), __expf(ra.y));
            Ri1[m] = bf2pack(__expf(rb.x), __expf(rb.y));
        }

        // numerator over s in (mid, L)
        float num = 0.0f;
        for (int s = mid + 1 + lane; s < L; s += 32) {
            int tp = tags[base + s - 1];
            int tc = tags[base + s];
            num += trans[tp * T_ + tc] + em[s * T_ + tc];
        }
#pragma unroll
        for (int o = 16; o > 0; o >>= 1) num += __shfl_xor_sync(FULLMASK, num, o);
        if (lane == 0) {
            int tgl = tags[base + L - 1];
            num += endt[tgl];
        }

        // init: u_{L-1} = exp(end) o exp(em[L-1])
        float2 eL = ep[(L - 1) * (T_ / 2) + lane];
        float u0f = __expf(endt[j0]) * __expf(eL.x);
        float u1f = __expf(endt[j1]) * __expf(eL.y);
        bf2 u2 = bf2pack(u0f, u1f);

        float2 p1 = ep[(L - 2) * (T_ / 2) + lane];
        float2 p2 = ep[(L - 3) * (T_ / 2) + lane];

        float r;
        int   kpend;
        {
            float u00 = __shfl_sync(FULLMASK, u0f, 0);
            int k = ((__float_as_int(u00) >> 23) & 0xff) - 127;
            k = max(-126, min(126, k));
            r = __int_as_float((127 - k) << 23);
            kpend = k;
        }
        float csum = 0.0f;

        const bf2 z2 = bf2pack(0.0f, 0.0f);

        for (int t = L - 2; t >= mid; t--) {
            const int pb = t & 1;
            sh_w[wid][pb][lane] = u2;
            __syncwarp();

            // F_t = exp(em[t]) (p1 currently holds em[t]); advance prefetch
            float Fn0 = __expf(p1.x);
            float Fn1 = __expf(p1.y);
            p1 = p2;
            int tp2 = t - 2; if (tp2 < 0) tp2 = 0;
            p2 = ep[tp2 * (T_ / 2) + lane];
            // final step (t==mid): produce beta_mid (no emission factor)
            bf2 Fr2 = (t == mid) ? bf2pack(r, r) : bf2pack(Fn0 * r, Fn1 * r);

            // matvec: v[i] = sum_j E[i][j] * u[j]
            const uint4* q = (const uint4*)sh_w[wid][pb];
            bf2 a00 = z2, a01 = z2, a02 = z2, a03 = z2;    // output row j0
            bf2 a10 = z2, a11 = z2, a12 = z2, a13 = z2;    // output row j1
#pragma unroll
            for (int g = 0; g < 8; g++) {
                uint4 v = q[g];
                bf2 us0 = bits2bf2(v.x);
                bf2 us1 = bits2bf2(v.y);
                bf2 us2 = bits2bf2(v.z);
                bf2 us3 = bits2bf2(v.w);
                a00 = __hfma2(us0, Ri0[4 * g + 0], a00);
                a01 = __hfma2(us1, Ri0[4 * g + 1], a01);
                a02 = __hfma2(us2, Ri0[4 * g + 2], a02);
                a03 = __hfma2(us3, Ri0[4 * g + 3], a03);
                a10 = __hfma2(us0, Ri1[4 * g + 0], a10);
                a11 = __hfma2(us1, Ri1[4 * g + 1], a11);
                a12 = __hfma2(us2, Ri1[4 * g + 2], a12);
                a13 = __hfma2(us3, Ri1[4 * g + 3], a13);
            }
            bf2 s0 = __hadd2(__hadd2(a00, a01), __hadd2(a02, a03));
            bf2 s1 = __hadd2(__hadd2(a10, a11), __hadd2(a12, a13));
            unsigned v0 = bf2bits(s0), v1 = bf2bits(s1);
            bf2 lo2 = bits2bf2(__byte_perm(v0, v1, 0x5410));
            bf2 hi2 = bits2bf2(__byte_perm(v0, v1, 0x7632));
            u2 = __hmul2(__hadd2(lo2, hi2), Fr2);

            csum += (float)kpend;

            unsigned uw = __shfl_sync(FULLMASK, bf2bits(u2), 0);
            int k = (int)((uw >> 7) & 0xff) - 127;
            k = max(-126, min(126, k));
            r = __int_as_float((127 - k) << 23);
            kpend = k;
        }

        __syncthreads();

        // ---- join: Z = sum_i alpha_mid[i] * beta_mid[i] ----
        float2 a = *(const float2*)&sh_a[pair][j0];
        float2 bb = __bfloat1622float2(u2);   // beta_mid (scaled)
        float e = a.x * bb.x + a.y * bb.y;
#pragma unroll
        for (int o = 16; o > 0; o >>= 1) e += __shfl_xor_sync(FULLMASK, e, o);
        if (lane == 0) {
            float csF  = sh_sc[pair][0];
            float numF = sh_sc[pair][1];
            float den = (float)(((double)csF + (double)csum) * 0.6931471805599453)
                        + __logf(e);
            g_ll[b]  = (numF + num) - den;
            g_len[b] = (float)L;
        }
        return;
    }
    // forward warps arrive here
    __syncthreads();
}

__global__ void crf_finalize(float* __restrict__ out) {
    __shared__ float s_ll[16];
    __shared__ float s_ln[16];
    int t = threadIdx.x;  // 512 threads
    float ll = g_ll[t];
    float ln = g_len[t];
#pragma unroll
    for (int o = 16; o > 0; o >>= 1) {
        ll += __shfl_xor_sync(FULLMASK, ll, o);
        ln += __shfl_xor_sync(FULLMASK, ln, o);
    }
    int w = t >> 5;
    if ((t & 31) == 0) { s_ll[w] = ll; s_ln[w] = ln; }
    __syncthreads();
    if (t == 0) {
        float sll = 0.0f, sln = 0.0f;
#pragma unroll
        for (int i = 0; i < 16; i++) { sll += s_ll[i]; sln += s_ln[i]; }
        out[0] = -(sll / sln);
    }
}

extern "C" void kernel_launch(void* const* d_in, const int* in_sizes, int n_in,
                              void* d_out, int out_size) {
    const float* emis  = (const float*)d_in[0];
    const int*   tags  = (const int*)d_in[1];
    const int*   mask  = (const int*)d_in[2];
    const float* start = (const float*)d_in[3];
    const float* endt  = (const float*)d_in[4];
    const float* trans = (const float*)d_in[5];
    float* out = (float*)d_out;

    crf_main<<<B_ / 8, 512>>>(emis, tags, mask, start, endt, trans);
    crf_finalize<<<1, B_>>>(out);
}